// round 2
// baseline (speedup 1.0000x reference)
#include <cuda_runtime.h>

#define TT 1024
#define BX 128
#define DD 64
#define CS 7          // steps per chunk (chunk 0 gets CS+1) ; 1 + 7*146 = 1023
#define NCHUNK 146
#define SR 65         // smem row stride in floats ([i][d] layout, 65 mod 32 = 1 -> conflict free)

// Phase 1: block b computes LOCAL prefix products of the per-step multipliers
//   m_s[i][j] = 1 + 1023 * <dX_s[i], dY_s[j]>
// over its step range, writing out[i,j,s+1] = local product through step s.
//   block 0   : steps [0, 8)
//   block b>0 : steps [7b+1, 7b+8)
__global__ __launch_bounds__(256, 1)
void nsk_phase1(const float4* __restrict__ X4, const float4* __restrict__ Y4,
                float* __restrict__ out) {
    extern __shared__ float smem[];
    float* sX = smem;             // [128][SR]
    float* sY = smem + BX * SR;   // [128][SR]

    const int tid = threadIdx.x;
    const int tx = tid & 15;      // j lane group / d-quad (loader)
    const int ty = tid >> 4;      // i lane group / row (loader)
    const int b = blockIdx.x;
    const int s_start = (b == 0) ? 0 : CS * b + 1;
    const int s_end = CS * b + CS + 1;      // 7b+8, max 1023 at b=145

    float k[8][8];
#pragma unroll
    for (int a = 0; a < 8; a++)
#pragma unroll
        for (int c = 0; c < 8; c++) k[a][c] = 1.0f;

    for (int s = s_start; s < s_end; ++s) {
        __syncthreads();   // previous iteration's readers done before overwrite

        // ---- load dX, dY for step s into smem ([i][d], i-major)
#pragma unroll
        for (int pass = 0; pass < 8; ++pass) {
            const int i = ty + 16 * pass;
            const int g = i * (TT * 16) + s * 16 + tx;   // float4 index of (i, s, 4*tx)
            float4 a0 = X4[g];
            float4 a1 = X4[g + 16];
            float4 c0 = Y4[g];
            float4 c1 = Y4[g + 16];
            const int sa = i * SR + 4 * tx;
            sX[sa + 0] = a1.x - a0.x;
            sX[sa + 1] = a1.y - a0.y;
            sX[sa + 2] = a1.z - a0.z;
            sX[sa + 3] = a1.w - a0.w;
            sY[sa + 0] = c1.x - c0.x;
            sY[sa + 1] = c1.y - c0.y;
            sY[sa + 2] = c1.z - c0.z;
            sY[sa + 3] = c1.w - c0.w;
        }
        __syncthreads();

        // ---- 8x8 per-thread micro-tile dot products over d
        float acc[8][8];
#pragma unroll
        for (int ri = 0; ri < 8; ri++)
#pragma unroll
            for (int rj = 0; rj < 8; rj++) acc[ri][rj] = 0.0f;

#pragma unroll 8
        for (int d = 0; d < DD; ++d) {
            float by[8];
#pragma unroll
            for (int rj = 0; rj < 8; rj++) by[rj] = sY[(tx + 16 * rj) * SR + d];
#pragma unroll
            for (int ri = 0; ri < 8; ri++) {
                const float ax = sX[(ty + 16 * ri) * SR + d];
#pragma unroll
                for (int rj = 0; rj < 8; rj++)
                    acc[ri][rj] = fmaf(ax, by[rj], acc[ri][rj]);
            }
        }

        // ---- k *= (1 + 1023*dot) ; write out[t = s+1]
#pragma unroll
        for (int ri = 0; ri < 8; ri++) {
#pragma unroll
            for (int rj = 0; rj < 8; rj++) {
                const int i = ty + 16 * ri;
                const int j = tx + 16 * rj;
                float kk = k[ri][rj];
                kk = fmaf(acc[ri][rj] * 1023.0f, kk, kk);
                k[ri][rj] = kk;
                out[(size_t)(i * BX + j) * TT + (s + 1)] = kk;
            }
        }
    }
}

// Phase 2: per (i,j) row, exclusive-scan the 146 chunk totals, rescale all t,
// and set t=0 to 1.
__global__ void nsk_phase2(float* __restrict__ out) {
    __shared__ float sc[NCHUNK];
    float* row = out + (size_t)blockIdx.x * TT;
    const int tid = threadIdx.x;

    if (tid < NCHUNK) {
        const int e = CS * tid + CS + 1;   // last t written by chunk `tid` (tid=0 -> 8)
        sc[tid] = row[e];
    }
    __syncthreads();
    if (tid == 0) {
        float p = 1.0f;
#pragma unroll 1
        for (int c = 0; c < NCHUNK; c++) { float v = sc[c]; sc[c] = p; p *= v; }
    }
    __syncthreads();
    for (int t = tid; t < TT; t += blockDim.x) {
        if (t == 0) {
            row[0] = 1.0f;
        } else {
            // chunk 0 owns t in [1, 8]; chunk b>=1 owns t in [7b+2, 7b+8]
            const int c = (t <= CS + 1) ? 0 : (t - 2) / CS;
            row[t] *= sc[c];
        }
    }
}

extern "C" void kernel_launch(void* const* d_in, const int* in_sizes, int n_in,
                              void* d_out, int out_size) {
    const float4* X4 = (const float4*)d_in[0];
    const float4* Y4 = (const float4*)d_in[1];
    float* out = (float*)d_out;

    const int smem_bytes = 2 * BX * SR * (int)sizeof(float);  // 66560 B
    cudaFuncSetAttribute(nsk_phase1, cudaFuncAttributeMaxDynamicSharedMemorySize,
                         smem_bytes);

    nsk_phase1<<<NCHUNK, 256, smem_bytes>>>(X4, Y4, out);
    nsk_phase2<<<BX * BX, 256>>>(out);
}

// round 3
// speedup vs baseline: 2.0427x; 2.0427x over previous
#include <cuda_runtime.h>

#define TT 1024
#define BX 128
#define NIJ (BX * BX)
#define DD 64
#define CS 8           // steps per chunk; 128 chunks * 8 = 1024 (last chunk has 7)
#define NCHUNK 128
#define SR2 65         // smem row stride in float2 ([i][d] layout)

// scratch: local prefix products in [t][i][j] layout (t in [1,1023]); 64 MB
__device__ float g_scratch[TT * NIJ];
// exclusive chunk-prefix scales, [c][ij] layout; 8 MB
__device__ float g_scales[NCHUNK * NIJ];

// Packed f32x2 FMA: acc.lo += a.lo*b.lo; acc.hi += a.hi*b.hi
__device__ __forceinline__ void fma2(unsigned long long &acc,
                                     unsigned long long a,
                                     unsigned long long b) {
    asm("fma.rn.f32x2 %0, %1, %2, %0;" : "+l"(acc) : "l"(a), "l"(b));
}

// Phase 1: block b computes LOCAL prefix products of per-step multipliers
//   m_s[i][j] = 1 + 1023 * <dX_s[i], dY_s[j]>
// over steps [8b, min(8b+8, 1023)), two steps per tile-load via f32x2 lanes.
// Writes scratch[t][i][j] (coalesced) for t = s+1 of each owned step s.
__global__ __launch_bounds__(256, 1)
void nsk_phase1(const float4* __restrict__ X4, const float4* __restrict__ Y4) {
    extern __shared__ float2 smem[];
    float2* sX = smem;               // [128][SR2]  lane0 = step s diff * 1023, lane1 = step s+1
    float2* sY = smem + BX * SR2;    // [128][SR2]  (unscaled)

    const int tid = threadIdx.x;
    const int tx = tid & 15;         // j lane group
    const int ty = tid >> 4;         // i lane group
    const int b = blockIdx.x;
    const int s_start = CS * b;
    const int s_end = min(CS * b + CS, TT - 1);

    float k[8][8];
#pragma unroll
    for (int a = 0; a < 8; a++)
#pragma unroll
        for (int c = 0; c < 8; c++) k[a][c] = 1.0f;

    const unsigned long long* uX = (const unsigned long long*)sX;
    const unsigned long long* uY = (const unsigned long long*)sY;

    for (int s = s_start; s < s_end; s += 2) {
        const int r2 = min(s + 2, TT - 1);  // clamp: tail lane gets diff 0
        __syncthreads();

        // ---- load dX (x1023) / dY for steps s, s+1 into [i][d] float2 smem
#pragma unroll
        for (int pass = 0; pass < 8; ++pass) {
            const int i = ty + 16 * pass;
            const int g = i * (TT * 16) + s * 16 + tx;   // float4 idx of (i, s, 4tx)
            float4 a0 = X4[g];
            float4 a1 = X4[g + 16];
            float4 a2 = X4[i * (TT * 16) + r2 * 16 + tx];
            const int sa = i * SR2 + 4 * tx;
            sX[sa + 0] = make_float2((a1.x - a0.x) * 1023.0f, (a2.x - a1.x) * 1023.0f);
            sX[sa + 1] = make_float2((a1.y - a0.y) * 1023.0f, (a2.y - a1.y) * 1023.0f);
            sX[sa + 2] = make_float2((a1.z - a0.z) * 1023.0f, (a2.z - a1.z) * 1023.0f);
            sX[sa + 3] = make_float2((a1.w - a0.w) * 1023.0f, (a2.w - a1.w) * 1023.0f);
            float4 c0 = Y4[g];
            float4 c1 = Y4[g + 16];
            float4 c2 = Y4[i * (TT * 16) + r2 * 16 + tx];
            sY[sa + 0] = make_float2(c1.x - c0.x, c2.x - c1.x);
            sY[sa + 1] = make_float2(c1.y - c0.y, c2.y - c1.y);
            sY[sa + 2] = make_float2(c1.z - c0.z, c2.z - c1.z);
            sY[sa + 3] = make_float2(c1.w - c0.w, c2.w - c1.w);
        }
        __syncthreads();

        // ---- 8x8 micro-tile, f32x2 accumulate over d (two steps at once)
        unsigned long long acc[8][8];
#pragma unroll
        for (int ri = 0; ri < 8; ri++)
#pragma unroll
            for (int rj = 0; rj < 8; rj++) acc[ri][rj] = 0ULL;

#pragma unroll 8
        for (int d = 0; d < DD; ++d) {
            unsigned long long by[8];
#pragma unroll
            for (int rj = 0; rj < 8; rj++) by[rj] = uY[(tx + 16 * rj) * SR2 + d];
#pragma unroll
            for (int ri = 0; ri < 8; ri++) {
                const unsigned long long ax = uX[(ty + 16 * ri) * SR2 + d];
#pragma unroll
                for (int rj = 0; rj < 8; rj++) fma2(acc[ri][rj], ax, by[rj]);
            }
        }

        // ---- k *= (1 + z) for both steps; coalesced stores to scratch[t][i][j]
        const bool second = (s + 2 <= s_end);   // step s+1 owned by this chunk?
#pragma unroll
        for (int ri = 0; ri < 8; ri++) {
#pragma unroll
            for (int rj = 0; rj < 8; rj++) {
                const unsigned long long a = acc[ri][rj];
                const float zx = __int_as_float((unsigned int)(a & 0xffffffffu));
                const float zy = __int_as_float((unsigned int)(a >> 32));
                const int i = ty + 16 * ri;
                const int j = tx + 16 * rj;
                float kk = k[ri][rj];
                kk = fmaf(zx, kk, kk);
                g_scratch[(s + 1) * NIJ + i * BX + j] = kk;
                kk = fmaf(zy, kk, kk);     // zy==0 at clamped tail -> harmless
                if (second) g_scratch[(s + 2) * NIJ + i * BX + j] = kk;
                k[ri][rj] = kk;
            }
        }
    }
}

// Phase 2a: one thread per (i,j): exclusive prefix product of the 128 chunk
// totals (local value at each chunk's last t), stored [c][ij].
__global__ void nsk_scales() {
    const int ij = blockIdx.x * blockDim.x + threadIdx.x;
    float p = 1.0f;
#pragma unroll 4
    for (int c = 0; c < NCHUNK; c++) {
        const int e = min(CS * c + CS, TT - 1);   // last t written by chunk c
        const float v = g_scratch[e * NIJ + ij];
        g_scales[c * NIJ + ij] = p;
        p *= v;
    }
}

// Phase 2b: tiled transpose + scale: out[ij][t] = scratch[t][ij] * sc[ij][(t-1)>>3]
// 64 t x 64 ij tiles, both global sides coalesced.
__global__ __launch_bounds__(256, 4)
void nsk_final(float* __restrict__ out) {
    __shared__ float tile[64][65];
    __shared__ float ssc[9][65];

    const int t0 = blockIdx.x * 64;
    const int ij0 = blockIdx.y * 64;
    const int u = threadIdx.x & 63;
    const int v = threadIdx.x >> 6;          // 0..3
    const int cbase = (t0 == 0) ? 0 : (t0 / CS - 1);

    // load 64x64 tile of scratch (rows t, cols ij), coalesced in ij
#pragma unroll
    for (int r = 0; r < 16; r++) {
        const int t = t0 + v + 4 * r;        // t=0 row is garbage; discarded below
        tile[v + 4 * r][u] = g_scratch[t * NIJ + ij0 + u];
    }
    // load 9 chunk-scale rows for these 64 ij
    for (int w = v; w < 9; w += 4)
        ssc[w][u] = g_scales[(cbase + w) * NIJ + ij0 + u];
    __syncthreads();

    // write transposed: lanes sweep t (coalesced), v+4r sweeps ij
#pragma unroll
    for (int r = 0; r < 16; r++) {
        const int col = v + 4 * r;
        const int ij = ij0 + col;
        const int t = t0 + u;
        float val;
        if (t == 0) {
            val = 1.0f;
        } else {
            val = tile[u][col] * ssc[((t - 1) >> 3) - cbase][col];
        }
        out[(size_t)ij * TT + t] = val;
    }
}

extern "C" void kernel_launch(void* const* d_in, const int* in_sizes, int n_in,
                              void* d_out, int out_size) {
    const float4* X4 = (const float4*)d_in[0];
    const float4* Y4 = (const float4*)d_in[1];
    float* out = (float*)d_out;

    const int smem_bytes = 2 * BX * SR2 * (int)sizeof(float2);  // 133120 B
    cudaFuncSetAttribute(nsk_phase1, cudaFuncAttributeMaxDynamicSharedMemorySize,
                         smem_bytes);

    nsk_phase1<<<NCHUNK, 256, smem_bytes>>>(X4, Y4);
    nsk_scales<<<NIJ / 128, 128>>>();
    nsk_final<<<dim3(TT / 64, NIJ / 64), 256>>>(out);
}

// round 4
// speedup vs baseline: 2.0574x; 1.0072x over previous
#include <cuda_runtime.h>

#define TT 1024
#define BX 128
#define NIJ (BX * BX)
#define DD 64
#define CS 8           // steps per chunk; 128 chunks * 8 = 1024 (last chunk has 7)
#define NCHUNK 128
#define SR2 65         // smem row stride in float2 ([i][d] layout)

// scratch: local prefix products in [t][i][j] layout (t in [1,1023]); 64 MB
__device__ float g_scratch[TT * NIJ];

// Packed f32x2 FMA: acc.lo += a.lo*b.lo; acc.hi += a.hi*b.hi
__device__ __forceinline__ void fma2(unsigned long long &acc,
                                     unsigned long long a,
                                     unsigned long long b) {
    asm("fma.rn.f32x2 %0, %1, %2, %0;" : "+l"(acc) : "l"(a), "l"(b));
}

// Phase 1: block b computes LOCAL prefix products of per-step multipliers
//   m_s[i][j] = 1 + 1023 * <dX_s[i], dY_s[j]>
// over steps [8b, min(8b+8, 1023)), two steps at once via f32x2 lanes.
// The 8x8 micro-tile is computed in two rj-halves (8x4 each) so the live
// accumulator set stays at 64 regs -> no spills.
__global__ __launch_bounds__(256, 1)
void nsk_phase1(const float4* __restrict__ X4, const float4* __restrict__ Y4) {
    extern __shared__ float2 smem[];
    float2* sX = smem;               // [128][SR2]  lane0 = 1023*diff(s), lane1 = 1023*diff(s+1)
    float2* sY = smem + BX * SR2;    // [128][SR2]  unscaled diffs

    const int tid = threadIdx.x;
    const int tx = tid & 15;         // j lane group
    const int ty = tid >> 4;         // i lane group
    const int b = blockIdx.x;
    const int s_start = CS * b;
    const int s_end = min(CS * b + CS, TT - 1);

    float k[8][8];
#pragma unroll
    for (int a = 0; a < 8; a++)
#pragma unroll
        for (int c = 0; c < 8; c++) k[a][c] = 1.0f;

    const unsigned long long* uX = (const unsigned long long*)sX;
    const unsigned long long* uY = (const unsigned long long*)sY;

    for (int s = s_start; s < s_end; s += 2) {
        const int r2 = min(s + 2, TT - 1);  // clamp: tail lane gets diff 0
        __syncthreads();

        // ---- load dX (x1023) / dY for steps s, s+1 into [i][d] float2 smem
#pragma unroll
        for (int pass = 0; pass < 8; ++pass) {
            const int i = ty + 16 * pass;
            const int g = i * (TT * 16) + s * 16 + tx;
            float4 a0 = X4[g];
            float4 a1 = X4[g + 16];
            float4 a2 = X4[i * (TT * 16) + r2 * 16 + tx];
            const int sa = i * SR2 + 4 * tx;
            sX[sa + 0] = make_float2((a1.x - a0.x) * 1023.0f, (a2.x - a1.x) * 1023.0f);
            sX[sa + 1] = make_float2((a1.y - a0.y) * 1023.0f, (a2.y - a1.y) * 1023.0f);
            sX[sa + 2] = make_float2((a1.z - a0.z) * 1023.0f, (a2.z - a1.z) * 1023.0f);
            sX[sa + 3] = make_float2((a1.w - a0.w) * 1023.0f, (a2.w - a1.w) * 1023.0f);
            float4 c0 = Y4[g];
            float4 c1 = Y4[g + 16];
            float4 c2 = Y4[i * (TT * 16) + r2 * 16 + tx];
            sY[sa + 0] = make_float2(c1.x - c0.x, c2.x - c1.x);
            sY[sa + 1] = make_float2(c1.y - c0.y, c2.y - c1.y);
            sY[sa + 2] = make_float2(c1.z - c0.z, c2.z - c1.z);
            sY[sa + 3] = make_float2(c1.w - c0.w, c2.w - c1.w);
        }
        __syncthreads();

        const bool second = (s + 2 <= s_end);   // step s+1 owned by this chunk?

        // ---- two rj-halves of the 8x8 micro-tile (static unroll: indices const)
#pragma unroll
        for (int half = 0; half < 2; ++half) {
            unsigned long long acc[8][4];
#pragma unroll
            for (int ri = 0; ri < 8; ri++)
#pragma unroll
                for (int rj = 0; rj < 4; rj++) acc[ri][rj] = 0ULL;

#pragma unroll 8
            for (int d = 0; d < DD; ++d) {
                unsigned long long by[4];
#pragma unroll
                for (int rj = 0; rj < 4; rj++)
                    by[rj] = uY[(tx + 16 * (4 * half + rj)) * SR2 + d];
#pragma unroll
                for (int ri = 0; ri < 8; ri++) {
                    const unsigned long long ax = uX[(ty + 16 * ri) * SR2 + d];
#pragma unroll
                    for (int rj = 0; rj < 4; rj++) fma2(acc[ri][rj], ax, by[rj]);
                }
            }

            // ---- epilogue: k *= (1+z) twice, coalesced stores to scratch[t][i][j]
#pragma unroll
            for (int ri = 0; ri < 8; ri++) {
#pragma unroll
                for (int rj = 0; rj < 4; rj++) {
                    const unsigned long long a = acc[ri][rj];
                    const float zx = __int_as_float((unsigned int)(a & 0xffffffffu));
                    const float zy = __int_as_float((unsigned int)(a >> 32));
                    const int i = ty + 16 * ri;
                    const int j = tx + 16 * (4 * half + rj);
                    float kk = k[ri][4 * half + rj];
                    kk = fmaf(zx, kk, kk);
                    g_scratch[(s + 1) * NIJ + i * BX + j] = kk;
                    kk = fmaf(zy, kk, kk);     // zy==0 at clamped tail
                    if (second) g_scratch[(s + 2) * NIJ + i * BX + j] = kk;
                    k[ri][4 * half + rj] = kk;
                }
            }
        }
    }
}

// Phase 2 (fused): one block per 64-ij strip.
//  A) load the 128 chunk-end rows, exclusive-scan them in smem (4 quarter
//     scans + combine) -> per-(chunk,ij) global scale.
//  B) stream 16 t-tiles: read scratch[t][ij] (coalesced), apply scale,
//     transpose through smem, write out[ij][t] (coalesced).
__global__ __launch_bounds__(256, 2)
void nsk_phase2f(float* __restrict__ out) {
    extern __shared__ float sm[];
    float* cend = sm;                    // [128][64] -> exclusive scales
    float* qp = sm + NCHUNK * 64;        // [4][64]
    float* tile = qp + 4 * 64;           // [64][65]

    const int tid = threadIdx.x;
    const int lane = tid & 63;
    const int q = tid >> 6;              // 0..3
    const int ij0 = blockIdx.x * 64;

    // A1: load chunk-end values (local product at each chunk's last t)
    for (int c = q; c < NCHUNK; c += 4) {
        const int e = min(CS * c + CS, TT - 1);
        cend[c * 64 + lane] = g_scratch[(size_t)e * NIJ + ij0 + lane];
    }
    __syncthreads();

    // A2: per-quarter exclusive product scan (32 chunks each)
    {
        float p = 1.0f;
#pragma unroll 1
        for (int cc = 0; cc < 32; cc++) {
            const int c = 32 * q + cc;
            const float v = cend[c * 64 + lane];
            cend[c * 64 + lane] = p;
            p *= v;
        }
        qp[q * 64 + lane] = p;
    }
    __syncthreads();

    // A3: fold in quarter offsets
    if (q > 0) {
        float off = qp[lane];
        if (q > 1) off *= qp[64 + lane];
        if (q > 2) off *= qp[128 + lane];
#pragma unroll 1
        for (int cc = 0; cc < 32; cc++)
            cend[(32 * q + cc) * 64 + lane] *= off;
    }
    __syncthreads();

    // B: 16 tiles of 64 t-rows
#pragma unroll 1
    for (int ti = 0; ti < 16; ti++) {
        const int t0 = ti * 64;
#pragma unroll
        for (int rr = 0; rr < 16; rr++) {
            const int r = q + 4 * rr;
            const int t = t0 + r;
            const float v = g_scratch[(size_t)t * NIJ + ij0 + lane];
            const int c = (t - 1) >> 3;
            const float sc = (t == 0) ? 1.0f : cend[c * 64 + lane];
            tile[r * 65 + lane] = v * sc;
        }
        __syncthreads();
#pragma unroll
        for (int rr = 0; rr < 16; rr++) {
            const int col = q + 4 * rr;
            const int t = t0 + lane;
            const float val = (t == 0) ? 1.0f : tile[lane * 65 + col];
            out[(size_t)(ij0 + col) * TT + t] = val;
        }
        __syncthreads();
    }
}

extern "C" void kernel_launch(void* const* d_in, const int* in_sizes, int n_in,
                              void* d_out, int out_size) {
    const float4* X4 = (const float4*)d_in[0];
    const float4* Y4 = (const float4*)d_in[1];
    float* out = (float*)d_out;

    const int smem1 = 2 * BX * SR2 * (int)sizeof(float2);            // 133120 B
    const int smem2 = (NCHUNK * 64 + 4 * 64 + 64 * 65) * (int)sizeof(float);  // 50432 B
    cudaFuncSetAttribute(nsk_phase1, cudaFuncAttributeMaxDynamicSharedMemorySize, smem1);
    cudaFuncSetAttribute(nsk_phase2f, cudaFuncAttributeMaxDynamicSharedMemorySize, smem2);

    nsk_phase1<<<NCHUNK, 256, smem1>>>(X4, Y4);
    nsk_phase2f<<<NIJ / 64, 256, smem2>>>(out);
}

// round 6
// speedup vs baseline: 2.2374x; 1.0875x over previous
#include <cuda_runtime.h>

#define TT 1024
#define BX 128
#define NIJ (BX * BX)
#define DD 64
#define CS 8           // steps per chunk; 128 chunks * 8 = 1024 (last chunk has 7)
#define NCHUNK 128
#define SR2 65         // smem row stride in float2 ([i][d] layout)

// scratch: local prefix products in [t][i][j] layout (t in [1,1023]); 64 MB
__device__ float g_scratch[TT * NIJ];

// Packed f32x2 FMA: acc.lo += a.lo*b.lo; acc.hi += a.hi*b.hi
__device__ __forceinline__ void fma2(unsigned long long &acc,
                                     unsigned long long a,
                                     unsigned long long b) {
    asm("fma.rn.f32x2 %0, %1, %2, %0;" : "+l"(acc) : "l"(a), "l"(b));
}

// Phase 1: block b computes LOCAL prefix products of per-step multipliers
//   m_s[i][j] = 1 + 1023 * <dX_s[i], dY_s[j]>
// over steps [8b, min(8b+8, 1023)), two steps at once via f32x2 lanes.
// 512 threads, per-thread 4x8 (i x j) tile computed as two explicit 4x4
// halves so at most 32 accumulator registers are live at a time.
__global__ __launch_bounds__(512, 1)
void nsk_phase1(const float4* __restrict__ X4, const float4* __restrict__ Y4) {
    extern __shared__ float2 smem[];
    float2* sX = smem;               // [128][SR2] lane0 = 1023*diff(s), lane1 = 1023*diff(s+1)
    float2* sY = smem + BX * SR2;    // [128][SR2] unscaled diffs

    const int tid = threadIdx.x;
    const int tx = tid & 15;              // j group (j = tx + 16*rj, rj<8)
    const int ty = (tid >> 4) & 31;       // i group (i = ty + 32*ri, ri<4)
    const int lquad = tid & 15;           // loader: d-quad
    const int lrow = tid >> 4;            // loader: row 0..31
    const int b = blockIdx.x;
    const int s_start = CS * b;
    const int s_end = min(CS * b + CS, TT - 1);

    float k[4][8];
#pragma unroll
    for (int a = 0; a < 4; a++)
#pragma unroll
        for (int c = 0; c < 8; c++) k[a][c] = 1.0f;

    const unsigned long long* uX = (const unsigned long long*)sX;
    const unsigned long long* uY = (const unsigned long long*)sY;

    for (int s = s_start; s < s_end; s += 2) {
        const int r2 = min(s + 2, TT - 1);    // clamp: tail lane gets diff 0
        __syncthreads();

        // ---- load dX (x1023) / dY for steps s, s+1 into [i][d] float2 smem
#pragma unroll
        for (int pass = 0; pass < 4; ++pass) {
            const int i = lrow + 32 * pass;
            const int g = i * (TT * 16) + s * 16 + lquad;
            float4 a0 = X4[g];
            float4 a1 = X4[g + 16];
            float4 a2 = X4[i * (TT * 16) + r2 * 16 + lquad];
            const int sa = i * SR2 + 4 * lquad;
            sX[sa + 0] = make_float2((a1.x - a0.x) * 1023.0f, (a2.x - a1.x) * 1023.0f);
            sX[sa + 1] = make_float2((a1.y - a0.y) * 1023.0f, (a2.y - a1.y) * 1023.0f);
            sX[sa + 2] = make_float2((a1.z - a0.z) * 1023.0f, (a2.z - a1.z) * 1023.0f);
            sX[sa + 3] = make_float2((a1.w - a0.w) * 1023.0f, (a2.w - a1.w) * 1023.0f);
            float4 c0 = Y4[g];
            float4 c1 = Y4[g + 16];
            float4 c2 = Y4[i * (TT * 16) + r2 * 16 + lquad];
            sY[sa + 0] = make_float2(c1.x - c0.x, c2.x - c1.x);
            sY[sa + 1] = make_float2(c1.y - c0.y, c2.y - c1.y);
            sY[sa + 2] = make_float2(c1.z - c0.z, c2.z - c1.z);
            sY[sa + 3] = make_float2(c1.w - c0.w, c2.w - c1.w);
        }
        __syncthreads();

        const bool second = (s + 2 <= s_end);

        // ================= HALF A: rj = 0..3 =================
        {
            unsigned long long acc[4][4];
#pragma unroll
            for (int ri = 0; ri < 4; ri++)
#pragma unroll
                for (int rj = 0; rj < 4; rj++) acc[ri][rj] = 0ULL;

#pragma unroll 8
            for (int d = 0; d < DD; ++d) {
                unsigned long long by[4];
#pragma unroll
                for (int rj = 0; rj < 4; rj++)
                    by[rj] = uY[(tx + 16 * rj) * SR2 + d];
#pragma unroll
                for (int ri = 0; ri < 4; ri++) {
                    const unsigned long long ax = uX[(ty + 32 * ri) * SR2 + d];
#pragma unroll
                    for (int rj = 0; rj < 4; rj++) fma2(acc[ri][rj], ax, by[rj]);
                }
            }
#pragma unroll
            for (int ri = 0; ri < 4; ri++) {
#pragma unroll
                for (int rj = 0; rj < 4; rj++) {
                    const unsigned long long a = acc[ri][rj];
                    const float zx = __int_as_float((unsigned int)(a & 0xffffffffu));
                    const float zy = __int_as_float((unsigned int)(a >> 32));
                    const int i = ty + 32 * ri;
                    const int j = tx + 16 * rj;
                    float kk = k[ri][rj];
                    kk = fmaf(zx, kk, kk);
                    g_scratch[(s + 1) * NIJ + i * BX + j] = kk;
                    kk = fmaf(zy, kk, kk);
                    if (second) g_scratch[(s + 2) * NIJ + i * BX + j] = kk;
                    k[ri][rj] = kk;
                }
            }
        }
        // ================= HALF B: rj = 4..7 =================
        {
            unsigned long long acc[4][4];
#pragma unroll
            for (int ri = 0; ri < 4; ri++)
#pragma unroll
                for (int rj = 0; rj < 4; rj++) acc[ri][rj] = 0ULL;

#pragma unroll 8
            for (int d = 0; d < DD; ++d) {
                unsigned long long by[4];
#pragma unroll
                for (int rj = 0; rj < 4; rj++)
                    by[rj] = uY[(tx + 16 * (rj + 4)) * SR2 + d];
#pragma unroll
                for (int ri = 0; ri < 4; ri++) {
                    const unsigned long long ax = uX[(ty + 32 * ri) * SR2 + d];
#pragma unroll
                    for (int rj = 0; rj < 4; rj++) fma2(acc[ri][rj], ax, by[rj]);
                }
            }
#pragma unroll
            for (int ri = 0; ri < 4; ri++) {
#pragma unroll
                for (int rj = 0; rj < 4; rj++) {
                    const unsigned long long a = acc[ri][rj];
                    const float zx = __int_as_float((unsigned int)(a & 0xffffffffu));
                    const float zy = __int_as_float((unsigned int)(a >> 32));
                    const int i = ty + 32 * ri;
                    const int j = tx + 16 * (rj + 4);
                    float kk = k[ri][rj + 4];
                    kk = fmaf(zx, kk, kk);
                    g_scratch[(s + 1) * NIJ + i * BX + j] = kk;
                    kk = fmaf(zy, kk, kk);
                    if (second) g_scratch[(s + 2) * NIJ + i * BX + j] = kk;
                    k[ri][rj + 4] = kk;
                }
            }
        }
    }
}

// Phase 2 (fused): one block per 32-ij strip (512 blocks, 8 CTAs/SM).
//  A) load the 128 chunk-end rows, exclusive-scan them in smem (8 sub-scans
//     of 16 chunks + combine) -> per-(chunk,ij) global scale.
//  B) stream 16 t-tiles of 64 t x 32 ij: read scratch[t][ij] (coalesced,
//     lane32 sweeps ij), apply scale, transpose through smem, write
//     out[ij][t] (coalesced, lane64 sweeps t).
__global__ __launch_bounds__(256, 8)
void nsk_phase2f(float* __restrict__ out) {
    extern __shared__ float sm[];
    float* cend = sm;                    // [128][32] -> exclusive scales
    float* qp = sm + NCHUNK * 32;        // [8][32]
    float* tile = qp + 8 * 32;           // [64][33]

    const int tid = threadIdx.x;
    const int lane = tid & 31;           // ij lane (loads / scan)
    const int q = tid >> 5;              // 0..7
    const int lane64 = tid & 63;         // t lane (stores)
    const int colg = tid >> 6;           // 0..3 (store col group)
    const int ij0 = blockIdx.x * 32;

    // A1: load chunk-end values (local product at each chunk's last t)
#pragma unroll
    for (int cc = 0; cc < 16; cc++) {
        const int c = q + 8 * cc;
        const int e = min(CS * c + CS, TT - 1);
        cend[c * 32 + lane] = g_scratch[(size_t)e * NIJ + ij0 + lane];
    }
    __syncthreads();

    // A2: per-eighth exclusive product scan (16 chunks each)
    {
        float p = 1.0f;
#pragma unroll 1
        for (int cc = 0; cc < 16; cc++) {
            const int c = 16 * q + cc;
            const float v = cend[c * 32 + lane];
            cend[c * 32 + lane] = p;
            p *= v;
        }
        qp[q * 32 + lane] = p;
    }
    __syncthreads();

    // A3: fold in sub-scan offsets
    if (q > 0) {
        float off = qp[lane];
#pragma unroll
        for (int w = 1; w < 7; w++)
            if (q > w) off *= qp[w * 32 + lane];
#pragma unroll 1
        for (int cc = 0; cc < 16; cc++)
            cend[(16 * q + cc) * 32 + lane] *= off;
    }
    __syncthreads();

    // B: 16 tiles of 64 t-rows x 32 ij
#pragma unroll 1
    for (int ti = 0; ti < 16; ti++) {
        const int t0 = ti * 64;
        // load + scale: rows r = q + 8*rr (0..63), cols = lane (0..31)
#pragma unroll
        for (int rr = 0; rr < 8; rr++) {
            const int r = q + 8 * rr;
            const int t = t0 + r;
            if (t == 0) {
                tile[r * 33 + lane] = 1.0f;
            } else {
                const float v = g_scratch[(size_t)t * NIJ + ij0 + lane];
                tile[r * 33 + lane] = v * cend[((t - 1) >> 3) * 32 + lane];
            }
        }
        __syncthreads();
        // store transposed: lane64 sweeps t (0..63), col = colg + 4*cc (0..31)
#pragma unroll
        for (int cc = 0; cc < 8; cc++) {
            const int col = colg + 4 * cc;
            out[(size_t)(ij0 + col) * TT + t0 + lane64] = tile[lane64 * 33 + col];
        }
        __syncthreads();
    }
}

extern "C" void kernel_launch(void* const* d_in, const int* in_sizes, int n_in,
                              void* d_out, int out_size) {
    const float4* X4 = (const float4*)d_in[0];
    const float4* Y4 = (const float4*)d_in[1];
    float* out = (float*)d_out;

    const int smem1 = 2 * BX * SR2 * (int)sizeof(float2);                     // 133120 B
    const int smem2 = (NCHUNK * 32 + 8 * 32 + 64 * 33) * (int)sizeof(float);  // 25856 B
    cudaFuncSetAttribute(nsk_phase1, cudaFuncAttributeMaxDynamicSharedMemorySize, smem1);
    cudaFuncSetAttribute(nsk_phase2f, cudaFuncAttributeMaxDynamicSharedMemorySize, smem2);

    nsk_phase1<<<NCHUNK, 512, smem1>>>(X4, Y4);
    nsk_phase2f<<<NIJ / 32, 256, smem2>>>(out);
}

// round 7
// speedup vs baseline: 2.2400x; 1.0012x over previous
#include <cuda_runtime.h>

#define TT 1024
#define BX 128
#define NIJ (BX * BX)
#define DD 64
#define CS 8           // steps per chunk; 128 chunks * 8 = 1024 (last chunk has 7)
#define NCHUNK 128
#define SR2 66         // smem row stride in float2: even -> 16B-aligned rows, 33 ull2
#define SRU 33         // row stride in ulonglong2

// scratch: local prefix products in [t][i][j] layout (t in [1,1023]); 64 MB
__device__ float g_scratch[TT * NIJ];

// Packed f32x2 FMA: acc.lo += a.lo*b.lo; acc.hi += a.hi*b.hi
__device__ __forceinline__ void fma2(unsigned long long &acc,
                                     unsigned long long a,
                                     unsigned long long b) {
    asm("fma.rn.f32x2 %0, %1, %2, %0;" : "+l"(acc) : "l"(a), "l"(b));
}

// Phase 1: block b computes LOCAL prefix products of per-step multipliers
//   m_s[i][j] = 1 + 1023 * <dX_s[i], dY_s[j]>
// over steps [8b, min(8b+8, 1023)), two steps at once via f32x2 lanes.
// 512 threads, per-thread 4x8 (i x j) tile as two explicit 4x4 halves.
// d processed in PAIRS via LDS.128 (ulonglong2) to halve LDS instruction
// pressure: 8 LDS.128 feed 32 FFMA2 per d-pair per half.
__global__ __launch_bounds__(512, 1)
void nsk_phase1(const float4* __restrict__ X4, const float4* __restrict__ Y4) {
    extern __shared__ float2 smem[];
    float2* sX = smem;               // [128][SR2] lane0 = 1023*diff(s), lane1 = 1023*diff(s+1)
    float2* sY = smem + BX * SR2;    // [128][SR2] unscaled diffs

    const int tid = threadIdx.x;
    const int tx = tid & 15;              // j group (j = tx + 16*rj, rj<8)
    const int ty = (tid >> 4) & 31;       // i group (i = ty + 32*ri, ri<4)
    const int lquad = tid & 15;           // loader: d-quad
    const int lrow = tid >> 4;            // loader: row 0..31
    const int b = blockIdx.x;
    const int s_start = CS * b;
    const int s_end = min(CS * b + CS, TT - 1);

    float k[4][8];
#pragma unroll
    for (int a = 0; a < 4; a++)
#pragma unroll
        for (int c = 0; c < 8; c++) k[a][c] = 1.0f;

    const ulonglong2* uX = (const ulonglong2*)sX;
    const ulonglong2* uY = (const ulonglong2*)sY;

    for (int s = s_start; s < s_end; s += 2) {
        const int r2 = min(s + 2, TT - 1);    // clamp: tail lane gets diff 0
        __syncthreads();

        // ---- load dX (x1023) / dY for steps s, s+1 into [i][d] float2 smem
#pragma unroll
        for (int pass = 0; pass < 4; ++pass) {
            const int i = lrow + 32 * pass;
            const int g = i * (TT * 16) + s * 16 + lquad;
            float4 a0 = X4[g];
            float4 a1 = X4[g + 16];
            float4 a2 = X4[i * (TT * 16) + r2 * 16 + lquad];
            const int sa = i * SR2 + 4 * lquad;
            sX[sa + 0] = make_float2((a1.x - a0.x) * 1023.0f, (a2.x - a1.x) * 1023.0f);
            sX[sa + 1] = make_float2((a1.y - a0.y) * 1023.0f, (a2.y - a1.y) * 1023.0f);
            sX[sa + 2] = make_float2((a1.z - a0.z) * 1023.0f, (a2.z - a1.z) * 1023.0f);
            sX[sa + 3] = make_float2((a1.w - a0.w) * 1023.0f, (a2.w - a1.w) * 1023.0f);
            float4 c0 = Y4[g];
            float4 c1 = Y4[g + 16];
            float4 c2 = Y4[i * (TT * 16) + r2 * 16 + lquad];
            sY[sa + 0] = make_float2(c1.x - c0.x, c2.x - c1.x);
            sY[sa + 1] = make_float2(c1.y - c0.y, c2.y - c1.y);
            sY[sa + 2] = make_float2(c1.z - c0.z, c2.z - c1.z);
            sY[sa + 3] = make_float2(c1.w - c0.w, c2.w - c1.w);
        }
        __syncthreads();

        const bool second = (s + 2 <= s_end);

        // ================= HALF A: rj = 0..3 =================
        {
            unsigned long long acc[4][4];
#pragma unroll
            for (int ri = 0; ri < 4; ri++)
#pragma unroll
                for (int rj = 0; rj < 4; rj++) acc[ri][rj] = 0ULL;

#pragma unroll 8
            for (int d2 = 0; d2 < DD / 2; ++d2) {
                ulonglong2 by[4];
#pragma unroll
                for (int rj = 0; rj < 4; rj++)
                    by[rj] = uY[(tx + 16 * rj) * SRU + d2];
#pragma unroll
                for (int ri = 0; ri < 4; ri++) {
                    const ulonglong2 ax = uX[(ty + 32 * ri) * SRU + d2];
#pragma unroll
                    for (int rj = 0; rj < 4; rj++) {
                        fma2(acc[ri][rj], ax.x, by[rj].x);
                        fma2(acc[ri][rj], ax.y, by[rj].y);
                    }
                }
            }
#pragma unroll
            for (int ri = 0; ri < 4; ri++) {
#pragma unroll
                for (int rj = 0; rj < 4; rj++) {
                    const unsigned long long a = acc[ri][rj];
                    const float zx = __int_as_float((unsigned int)(a & 0xffffffffu));
                    const float zy = __int_as_float((unsigned int)(a >> 32));
                    const int i = ty + 32 * ri;
                    const int j = tx + 16 * rj;
                    float kk = k[ri][rj];
                    kk = fmaf(zx, kk, kk);
                    g_scratch[(s + 1) * NIJ + i * BX + j] = kk;
                    kk = fmaf(zy, kk, kk);
                    if (second) g_scratch[(s + 2) * NIJ + i * BX + j] = kk;
                    k[ri][rj] = kk;
                }
            }
        }
        // ================= HALF B: rj = 4..7 =================
        {
            unsigned long long acc[4][4];
#pragma unroll
            for (int ri = 0; ri < 4; ri++)
#pragma unroll
                for (int rj = 0; rj < 4; rj++) acc[ri][rj] = 0ULL;

#pragma unroll 8
            for (int d2 = 0; d2 < DD / 2; ++d2) {
                ulonglong2 by[4];
#pragma unroll
                for (int rj = 0; rj < 4; rj++)
                    by[rj] = uY[(tx + 16 * (rj + 4)) * SRU + d2];
#pragma unroll
                for (int ri = 0; ri < 4; ri++) {
                    const ulonglong2 ax = uX[(ty + 32 * ri) * SRU + d2];
#pragma unroll
                    for (int rj = 0; rj < 4; rj++) {
                        fma2(acc[ri][rj], ax.x, by[rj].x);
                        fma2(acc[ri][rj], ax.y, by[rj].y);
                    }
                }
            }
#pragma unroll
            for (int ri = 0; ri < 4; ri++) {
#pragma unroll
                for (int rj = 0; rj < 4; rj++) {
                    const unsigned long long a = acc[ri][rj];
                    const float zx = __int_as_float((unsigned int)(a & 0xffffffffu));
                    const float zy = __int_as_float((unsigned int)(a >> 32));
                    const int i = ty + 32 * ri;
                    const int j = tx + 16 * (rj + 4);
                    float kk = k[ri][rj + 4];
                    kk = fmaf(zx, kk, kk);
                    g_scratch[(s + 1) * NIJ + i * BX + j] = kk;
                    kk = fmaf(zy, kk, kk);
                    if (second) g_scratch[(s + 2) * NIJ + i * BX + j] = kk;
                    k[ri][rj + 4] = kk;
                }
            }
        }
    }
}

// Phase 2 (fused): one block per 32-ij strip (512 blocks, 8 CTAs/SM).
//  A) load the 128 chunk-end rows, exclusive-scan them in smem (8 sub-scans
//     of 16 chunks + combine) -> per-(chunk,ij) global scale.
//  B) stream 16 t-tiles of 64 t x 32 ij: read scratch[t][ij] (coalesced,
//     lane32 sweeps ij), apply scale, transpose through smem, write
//     out[ij][t] (coalesced, lane64 sweeps t).
__global__ __launch_bounds__(256, 8)
void nsk_phase2f(float* __restrict__ out) {
    extern __shared__ float sm[];
    float* cend = sm;                    // [128][32] -> exclusive scales
    float* qp = sm + NCHUNK * 32;        // [8][32]
    float* tile = qp + 8 * 32;           // [64][33]

    const int tid = threadIdx.x;
    const int lane = tid & 31;           // ij lane (loads / scan)
    const int q = tid >> 5;              // 0..7
    const int lane64 = tid & 63;         // t lane (stores)
    const int colg = tid >> 6;           // 0..3 (store col group)
    const int ij0 = blockIdx.x * 32;

    // A1: load chunk-end values (local product at each chunk's last t)
#pragma unroll
    for (int cc = 0; cc < 16; cc++) {
        const int c = q + 8 * cc;
        const int e = min(CS * c + CS, TT - 1);
        cend[c * 32 + lane] = g_scratch[(size_t)e * NIJ + ij0 + lane];
    }
    __syncthreads();

    // A2: per-eighth exclusive product scan (16 chunks each)
    {
        float p = 1.0f;
#pragma unroll 1
        for (int cc = 0; cc < 16; cc++) {
            const int c = 16 * q + cc;
            const float v = cend[c * 32 + lane];
            cend[c * 32 + lane] = p;
            p *= v;
        }
        qp[q * 32 + lane] = p;
    }
    __syncthreads();

    // A3: fold in sub-scan offsets
    if (q > 0) {
        float off = qp[lane];
#pragma unroll
        for (int w = 1; w < 7; w++)
            if (q > w) off *= qp[w * 32 + lane];
#pragma unroll 1
        for (int cc = 0; cc < 16; cc++)
            cend[(16 * q + cc) * 32 + lane] *= off;
    }
    __syncthreads();

    // B: 16 tiles of 64 t-rows x 32 ij
#pragma unroll 1
    for (int ti = 0; ti < 16; ti++) {
        const int t0 = ti * 64;
        // load + scale: rows r = q + 8*rr (0..63), cols = lane (0..31)
#pragma unroll
        for (int rr = 0; rr < 8; rr++) {
            const int r = q + 8 * rr;
            const int t = t0 + r;
            if (t == 0) {
                tile[r * 33 + lane] = 1.0f;
            } else {
                const float v = g_scratch[(size_t)t * NIJ + ij0 + lane];
                tile[r * 33 + lane] = v * cend[((t - 1) >> 3) * 32 + lane];
            }
        }
        __syncthreads();
        // store transposed: lane64 sweeps t (0..63), col = colg + 4*cc (0..31)
#pragma unroll
        for (int cc = 0; cc < 8; cc++) {
            const int col = colg + 4 * cc;
            out[(size_t)(ij0 + col) * TT + t0 + lane64] = tile[lane64 * 33 + col];
        }
        __syncthreads();
    }
}

extern "C" void kernel_launch(void* const* d_in, const int* in_sizes, int n_in,
                              void* d_out, int out_size) {
    const float4* X4 = (const float4*)d_in[0];
    const float4* Y4 = (const float4*)d_in[1];
    float* out = (float*)d_out;

    const int smem1 = 2 * BX * SR2 * (int)sizeof(float2);                     // 135168 B
    const int smem2 = (NCHUNK * 32 + 8 * 32 + 64 * 33) * (int)sizeof(float);  // 25856 B
    cudaFuncSetAttribute(nsk_phase1, cudaFuncAttributeMaxDynamicSharedMemorySize, smem1);
    cudaFuncSetAttribute(nsk_phase2f, cudaFuncAttributeMaxDynamicSharedMemorySize, smem2);

    nsk_phase1<<<NCHUNK, 512, smem1>>>(X4, Y4);
    nsk_phase2f<<<NIJ / 32, 256, smem2>>>(out);
}

// round 9
// speedup vs baseline: 2.7576x; 1.2310x over previous
#include <cuda_runtime.h>
#include <cuda_bf16.h>
#include <cstdint>

#define TT 1024
#define BX 128
#define NIJ (BX * BX)
#define CS 8
#define NCHUNK 128
#define SAB 200          // smem bf16 row stride (400 B; 400 mod 128 = 16 -> ldmatrix conflict-free)

// scratch: local prefix products, layout [t][i*128+j]; 64 MB
__device__ float g_scratch[TT * NIJ];

__device__ __forceinline__ uint32_t smem_u32(const void* p) {
    uint32_t a;
    asm("{ .reg .u64 t; cvta.to.shared.u64 t, %1; cvt.u32.u64 %0, t; }"
        : "=r"(a) : "l"(p));
    return a;
}

__device__ __forceinline__ void ldsm_x4(uint32_t& r0, uint32_t& r1,
                                        uint32_t& r2, uint32_t& r3,
                                        uint32_t addr) {
    asm volatile("ldmatrix.sync.aligned.m8n8.x4.shared.b16 {%0,%1,%2,%3}, [%4];"
                 : "=r"(r0), "=r"(r1), "=r"(r2), "=r"(r3) : "r"(addr));
}

__device__ __forceinline__ void mma16816(float* c, const uint32_t* a,
                                         uint32_t b0, uint32_t b1) {
    asm volatile(
        "mma.sync.aligned.m16n8k16.row.col.f32.bf16.bf16.f32 "
        "{%0,%1,%2,%3}, {%4,%5,%6,%7}, {%8,%9}, {%0,%1,%2,%3};"
        : "+f"(c[0]), "+f"(c[1]), "+f"(c[2]), "+f"(c[3])
        : "r"(a[0]), "r"(a[1]), "r"(a[2]), "r"(a[3]), "r"(b0), "r"(b1));
}

__device__ __forceinline__ uint32_t bcat(__nv_bfloat16 a, __nv_bfloat16 b) {
    __nv_bfloat162 t = __halves2bfloat162(a, b);
    return *reinterpret_cast<uint32_t*>(&t);
}

// Phase 1 (HMMA): block b handles steps [8b, min(8b+8,1023)). Per step:
// dX*1023 and dY are split into bf16 (hi, lo); K=192 concat layout
//   A = [Xhi | Xhi | Xlo],  B = [Yhi | Ylo | Yhi]
// so one K-pass accumulates hi*hi + hi*lo + lo*hi in fp32 via mma.sync.
// 16 warps in a 4x4 grid, each computing a 32x32 tile of Z, then updating
// its running products k and storing scratch[t][i*128+j].
__global__ __launch_bounds__(512, 1)
void nsk_phase1(const float4* __restrict__ X4, const float4* __restrict__ Y4) {
    extern __shared__ __nv_bfloat16 smb[];
    __nv_bfloat16* sA = smb;                 // [128][SAB]
    __nv_bfloat16* sB = smb + 128 * SAB;     // [128][SAB]
    const uint32_t aA = smem_u32(sA);
    const uint32_t aB = smem_u32(sB);

    const int tid = threadIdx.x;
    const int wid = tid >> 5;
    const int lane = tid & 31;

    // conversion role
    const int crow = tid >> 2;           // 0..127
    const int cq = tid & 3;              // d-quad of 16
    // mma tile role
    const int m0 = (wid >> 2) * 32;
    const int n0 = (wid & 3) * 32;
    const int grp = lane >> 3, lrow = lane & 7;
    const uint32_t offA = (uint32_t)((lrow + 8 * (grp & 1)) * 400 + 16 * (grp >> 1));
    const uint32_t offB = (uint32_t)((lrow + 8 * (grp >> 1)) * 400 + 16 * (grp & 1));
    const int g = lane >> 2, tg = lane & 3;

    const int b = blockIdx.x;
    const int s0 = CS * b;
    const int s1 = min(s0 + CS, TT - 1);

    float k[2][4][4];
#pragma unroll
    for (int a = 0; a < 2; a++)
#pragma unroll
        for (int c = 0; c < 4; c++)
#pragma unroll
            for (int e = 0; e < 4; e++) k[a][c][e] = 1.0f;

    for (int s = s0; s < s1; ++s) {
        __syncthreads();   // all warps done reading smem from previous step

        // ---- convert: 16 d-values per thread -> hi/lo bf16, K=192 layout
        {
            const int gb = crow * 16384 + s * 16 + cq * 4;
            float fx[16], fy[16];
#pragma unroll
            for (int c = 0; c < 4; ++c) {
                float4 a0 = X4[gb + c], a1 = X4[gb + 16 + c];
                fx[4 * c + 0] = (a1.x - a0.x) * 1023.0f;
                fx[4 * c + 1] = (a1.y - a0.y) * 1023.0f;
                fx[4 * c + 2] = (a1.z - a0.z) * 1023.0f;
                fx[4 * c + 3] = (a1.w - a0.w) * 1023.0f;
                float4 b0 = Y4[gb + c], b1 = Y4[gb + 16 + c];
                fy[4 * c + 0] = b1.x - b0.x;
                fy[4 * c + 1] = b1.y - b0.y;
                fy[4 * c + 2] = b1.z - b0.z;
                fy[4 * c + 3] = b1.w - b0.w;
            }
            uint32_t xh[8], xl[8], yh[8], yl[8];
#pragma unroll
            for (int m = 0; m < 8; ++m) {
                float u = fx[2 * m], v = fx[2 * m + 1];
                __nv_bfloat16 uh = __float2bfloat16_rn(u);
                __nv_bfloat16 vh = __float2bfloat16_rn(v);
                xh[m] = bcat(uh, vh);
                xl[m] = bcat(__float2bfloat16_rn(u - __bfloat162float(uh)),
                             __float2bfloat16_rn(v - __bfloat162float(vh)));
                float p = fy[2 * m], q = fy[2 * m + 1];
                __nv_bfloat16 ph = __float2bfloat16_rn(p);
                __nv_bfloat16 qh = __float2bfloat16_rn(q);
                yh[m] = bcat(ph, qh);
                yl[m] = bcat(__float2bfloat16_rn(p - __bfloat162float(ph)),
                             __float2bfloat16_rn(q - __bfloat162float(qh)));
            }
            char* pa = (char*)sA + crow * 400 + cq * 32;
            ((uint4*)pa)[0] = ((uint4*)xh)[0];
            ((uint4*)(pa + 16))[0] = ((uint4*)xh)[1];
            ((uint4*)(pa + 128))[0] = ((uint4*)xh)[0];      // Xhi copy 2
            ((uint4*)(pa + 144))[0] = ((uint4*)xh)[1];
            ((uint4*)(pa + 256))[0] = ((uint4*)xl)[0];      // Xlo
            ((uint4*)(pa + 272))[0] = ((uint4*)xl)[1];
            char* pb = (char*)sB + crow * 400 + cq * 32;
            ((uint4*)pb)[0] = ((uint4*)yh)[0];              // Yhi
            ((uint4*)(pb + 16))[0] = ((uint4*)yh)[1];
            ((uint4*)(pb + 128))[0] = ((uint4*)yl)[0];      // Ylo
            ((uint4*)(pb + 144))[0] = ((uint4*)yl)[1];
            ((uint4*)(pb + 256))[0] = ((uint4*)yh)[0];      // Yhi copy 2
            ((uint4*)(pb + 272))[0] = ((uint4*)yh)[1];
        }
        __syncthreads();

        // ---- 12 k-chunks of 16 over the K=192 concat
        float cacc[2][4][4];
#pragma unroll
        for (int mf = 0; mf < 2; mf++)
#pragma unroll
            for (int nf = 0; nf < 4; nf++)
#pragma unroll
                for (int e = 0; e < 4; e++) cacc[mf][nf][e] = 0.0f;

#pragma unroll
        for (int kc = 0; kc < 12; ++kc) {
            const uint32_t kb = kc * 32;
            uint32_t af0[4], af1[4], b0r[4], b1r[4];
            ldsm_x4(af0[0], af0[1], af0[2], af0[3], aA + m0 * 400 + kb + offA);
            ldsm_x4(af1[0], af1[1], af1[2], af1[3], aA + (m0 + 16) * 400 + kb + offA);
            ldsm_x4(b0r[0], b0r[1], b0r[2], b0r[3], aB + n0 * 400 + kb + offB);
            ldsm_x4(b1r[0], b1r[1], b1r[2], b1r[3], aB + (n0 + 16) * 400 + kb + offB);
            mma16816(cacc[0][0], af0, b0r[0], b0r[1]);
            mma16816(cacc[0][1], af0, b0r[2], b0r[3]);
            mma16816(cacc[0][2], af0, b1r[0], b1r[1]);
            mma16816(cacc[0][3], af0, b1r[2], b1r[3]);
            mma16816(cacc[1][0], af1, b0r[0], b0r[1]);
            mma16816(cacc[1][1], af1, b0r[2], b0r[3]);
            mma16816(cacc[1][2], af1, b1r[0], b1r[1]);
            mma16816(cacc[1][3], af1, b1r[2], b1r[3]);
        }

        // ---- epilogue: k *= (1+z); float2 stores (8 sectors per warp-store)
        float* base = g_scratch + (size_t)(s + 1) * NIJ;
#pragma unroll
        for (int mf = 0; mf < 2; mf++) {
#pragma unroll
            for (int nf = 0; nf < 4; nf++) {
                const int i0 = m0 + mf * 16 + g;
                const int j = n0 + nf * 8 + tg * 2;
                float* c4 = cacc[mf][nf];
                float* kk = k[mf][nf];
                float k0 = fmaf(c4[0], kk[0], kk[0]);
                float k1 = fmaf(c4[1], kk[1], kk[1]);
                float k2 = fmaf(c4[2], kk[2], kk[2]);
                float k3 = fmaf(c4[3], kk[3], kk[3]);
                kk[0] = k0; kk[1] = k1; kk[2] = k2; kk[3] = k3;
                *(float2*)(base + i0 * BX + j) = make_float2(k0, k1);
                *(float2*)(base + (i0 + 8) * BX + j) = make_float2(k2, k3);
            }
        }
    }
}

// Phase 2 (fused): one block per 32-ij strip (512 blocks, 8 CTAs/SM).
// Scan 128 chunk totals -> exclusive scales; stream 16 t-tiles of 64t x 32ij;
// transpose through smem; both global sides coalesced.
__global__ __launch_bounds__(256, 8)
void nsk_phase2f(float* __restrict__ out) {
    extern __shared__ float sm[];
    float* cend = sm;                    // [128][32] -> exclusive scales
    float* qp = sm + NCHUNK * 32;        // [8][32]
    float* tile = qp + 8 * 32;           // [64][33]

    const int tid = threadIdx.x;
    const int lane = tid & 31;
    const int q = tid >> 5;              // 0..7
    const int lane64 = tid & 63;
    const int colg = tid >> 6;           // 0..3
    const int ij0 = blockIdx.x * 32;

#pragma unroll
    for (int cc = 0; cc < 16; cc++) {
        const int c = q + 8 * cc;
        const int e = min(CS * c + CS, TT - 1);
        cend[c * 32 + lane] = g_scratch[(size_t)e * NIJ + ij0 + lane];
    }
    __syncthreads();
    {
        float p = 1.0f;
#pragma unroll 1
        for (int cc = 0; cc < 16; cc++) {
            const int c = 16 * q + cc;
            const float v = cend[c * 32 + lane];
            cend[c * 32 + lane] = p;
            p *= v;
        }
        qp[q * 32 + lane] = p;
    }
    __syncthreads();
    if (q > 0) {
        float off = qp[lane];
#pragma unroll
        for (int w = 1; w < 7; w++)
            if (q > w) off *= qp[w * 32 + lane];
#pragma unroll 1
        for (int cc = 0; cc < 16; cc++)
            cend[(16 * q + cc) * 32 + lane] *= off;
    }
    __syncthreads();

#pragma unroll 1
    for (int ti = 0; ti < 16; ti++) {
        const int t0 = ti * 64;
#pragma unroll
        for (int rr = 0; rr < 8; rr++) {
            const int r = q + 8 * rr;
            const int t = t0 + r;
            if (t == 0) {
                tile[r * 33 + lane] = 1.0f;
            } else {
                const float v = g_scratch[(size_t)t * NIJ + ij0 + lane];
                tile[r * 33 + lane] = v * cend[((t - 1) >> 3) * 32 + lane];
            }
        }
        __syncthreads();
#pragma unroll
        for (int cc = 0; cc < 8; cc++) {
            const int col = colg + 4 * cc;
            out[(size_t)(ij0 + col) * TT + t0 + lane64] = tile[lane64 * 33 + col];
        }
        __syncthreads();
    }
}

extern "C" void kernel_launch(void* const* d_in, const int* in_sizes, int n_in,
                              void* d_out, int out_size) {
    const float4* X4 = (const float4*)d_in[0];
    const float4* Y4 = (const float4*)d_in[1];
    float* out = (float*)d_out;

    const int smem1 = 2 * 128 * SAB * (int)sizeof(__nv_bfloat16);             // 102400 B
    const int smem2 = (NCHUNK * 32 + 8 * 32 + 64 * 33) * (int)sizeof(float);  // 25856 B
    cudaFuncSetAttribute(nsk_phase1, cudaFuncAttributeMaxDynamicSharedMemorySize, smem1);
    cudaFuncSetAttribute(nsk_phase2f, cudaFuncAttributeMaxDynamicSharedMemorySize, smem2);

    nsk_phase1<<<NCHUNK, 512, smem1>>>(X4, Y4);
    nsk_phase2f<<<NIJ / 32, 256, smem2>>>(out);
}